// round 10
// baseline (speedup 1.0000x reference)
#include <cuda_runtime.h>
#include <math.h>

#define B_  32
#define T_  1024
#define C_  128
#define G_  896
#define G3_ 2688
#define H_  896
#define NB  112      // persistent CTAs for the scan (1/SM guaranteed by smem)

typedef unsigned long long u64;

// ---------------- device scratch (allocation-free: __device__ globals) -------
__device__ __align__(256) float g_gx [(size_t)T_ * G3_ * B_];  // [T][3G][B]
__device__ __align__(256) float g_hs2[(size_t)T_ * G_  * B_];  // [t/2][G][B][2]
__device__ __align__(256) float g_h  [2 * G_ * B_];            // double-buffered h, [G][B]

struct __align__(256) PadCnt { unsigned v; unsigned pad[63]; };
__device__ PadCnt g_cntA, g_cntB;   // zero-init; self-restoring
__device__ PadCnt g_genA, g_genB;   // zero-init; reset to 0 by closer at t=1023

// ---------------- helpers ----------------------------------------------------
__device__ __forceinline__ void fma2(u64 &acc, u64 a, u64 b) {
    asm("fma.rn.f32x2 %0, %1, %2, %0;" : "+l"(acc) : "l"(a), "l"(b));
}
__device__ __forceinline__ u64 pack2(float x, float y) {
    u64 r; asm("mov.b64 %0, {%1,%2};" : "=l"(r) : "f"(x), "f"(y)); return r;
}
__device__ __forceinline__ float2 unpack2(u64 v) {
    float2 r; asm("mov.b64 {%0,%1}, %2;" : "=f"(r.x), "=f"(r.y) : "l"(v)); return r;
}
__device__ __forceinline__ float sigm(float x) {
    return __fdividef(1.0f, 1.0f + __expf(-x));
}
__device__ __forceinline__ float tanh_fast(float x) {
    float e = __expf(2.0f * x);
    return 1.0f - __fdividef(2.0f, e + 1.0f);
}
__device__ __forceinline__ void cp_async16(float* smem_dst, const float* gsrc) {
    unsigned s = (unsigned)__cvta_generic_to_shared(smem_dst);
    asm volatile("cp.async.cg.shared.global [%0], [%1], 16;" :: "r"(s), "l"(gsrc));
}
#define CP_COMMIT() asm volatile("cp.async.commit_group;")
#define CP_WAIT(n)  asm volatile("cp.async.wait_group %0;" :: "n"(n))

__device__ __forceinline__ unsigned atom_add_acqrel(unsigned* p) {
    unsigned old;
    asm volatile("atom.acq_rel.gpu.global.add.u32 %0, [%1], 1;"
                 : "=r"(old) : "l"(p) : "memory");
    return old;
}
__device__ __forceinline__ unsigned ld_acquire(unsigned* p) {
    unsigned v;
    asm volatile("ld.acquire.gpu.global.u32 %0, [%1];" : "=r"(v) : "l"(p) : "memory");
    return v;
}
__device__ __forceinline__ void st_release(unsigned* p, unsigned v) {
    asm volatile("st.release.gpu.global.u32 [%0], %1;" :: "l"(p), "r"(v) : "memory");
}
__device__ __forceinline__ void st_relaxed(unsigned* p, unsigned v) {
    asm volatile("st.relaxed.gpu.global.u32 [%0], %1;" :: "l"(p), "r"(v) : "memory");
}

// ============================================================================
__global__ void k_nop() {}

// ============================================================================
// gx[t][row][b] = b_ih[row] + sum_c x[b][t][c] * w_ih[row][c]
// ============================================================================
__global__ __launch_bounds__(128) void k_gx(const float* __restrict__ x,
                                            const float* __restrict__ state,
                                            const float* __restrict__ w_ih,
                                            const float* __restrict__ b_ih) {
    __shared__ float ws[128 * 64];   // [c][r]
    __shared__ float xs[128 * 32];   // [c][b]
    const int tid = threadIdx.x;
    const int r0  = blockIdx.x * 64;
    const int t   = blockIdx.y;

    if (blockIdx.x == 0 && blockIdx.y == 0) {
        for (int i = tid; i < G_ * B_; i += 128) {
            int g = i >> 5, b = i & 31;
            g_h[g * 32 + b] = state[b * G_ + g];
        }
    }

    for (int i = tid; i < 64 * 32; i += 128) {
        int r = i >> 5, cq = (i & 31) * 4;
        float4 v = *(const float4*)(w_ih + (size_t)(r0 + r) * C_ + cq);
        ws[(cq+0)*64 + r] = v.x; ws[(cq+1)*64 + r] = v.y;
        ws[(cq+2)*64 + r] = v.z; ws[(cq+3)*64 + r] = v.w;
    }
    for (int i = tid; i < 32 * 32; i += 128) {
        int b = i >> 5, cq = (i & 31) * 4;
        float4 v = *(const float4*)(x + ((size_t)b * T_ + t) * C_ + cq);
        xs[(cq+0)*32 + b] = v.x; xs[(cq+1)*32 + b] = v.y;
        xs[(cq+2)*32 + b] = v.z; xs[(cq+3)*32 + b] = v.w;
    }
    __syncthreads();

    const int rt  = tid >> 3;
    const int bpt = tid & 7;
    const int rr  = rt * 4;
    const int bb  = bpt * 4;
    u64 acc[4][2] = {};

#pragma unroll 2
    for (int k = 0; k < 128; ++k) {
        const float* wk = ws + k * 64 + rr;
        u64 h0 = *(const u64*)(xs + k * 32 + bb);
        u64 h1 = *(const u64*)(xs + k * 32 + bb + 2);
#pragma unroll
        for (int i = 0; i < 4; ++i) {
            u64 wp = pack2(wk[i], wk[i]);
            fma2(acc[i][0], wp, h0);
            fma2(acc[i][1], wp, h1);
        }
    }
#pragma unroll
    for (int i = 0; i < 4; ++i) {
        float bias = b_ih[r0 + rr + i];
        float* op = g_gx + ((size_t)t * G3_ + r0 + rr + i) * B_ + bb;
        float2 a0 = unpack2(acc[i][0]); a0.x += bias; a0.y += bias;
        float2 a1 = unpack2(acc[i][1]); a1.x += bias; a1.y += bias;
        *(float2*)(op)     = a0;
        *(float2*)(op + 2) = a1;
    }
}

// ============================================================================
// Persistent GRU scan, 112 CTAs x 512 threads (16 warps).
// Batch split in two independent halves (b 0..15 / 16..31), each with its own
// grid barrier, PHASE-STAGGERED: half-B's compute hides half-A's barrier
// round-trip + h L2 latency, and vice versa. Warp w owns k-slice
// [w*56, w*56+56) for both halves. Reduction buffers alias the just-consumed
// half's hs. Epilogue on threads 0..127 (j = tid>>4, local b = tid&15).
// SMEM: ws 86016 + hsA 57344 + hsB 57344 = 200704 B -> 1 CTA/SM.
// ============================================================================
#define RNN_SMEM ((896*24 + G_*B_) * 4)   // 200704

__global__ __launch_bounds__(512) void k_rnn(const float* __restrict__ w_hh,
                                             const float* __restrict__ b_hh) {
    extern __shared__ float sm[];
    float* ws  = sm;                      // [896][24]  ws[k][g*8+j]
    float* hsA = sm + 896 * 24;           // [896][16]
    float* hsB = hsA + 896 * 16;          // [896][16]
    // red aliases hs (dead after that half's mainloop): rows of 17 u64
    u64*   redA  = (u64*)hsA;  float* redAf = hsA;
    u64*   redB  = (u64*)hsB;  float* redBf = hsB;

    const int tid  = threadIdx.x;
    const int warp = tid >> 5;
    const int lane = tid & 31;
    const int cta  = blockIdx.x;
    const int j0   = cta * 8;
    const int k0   = warp * 56;

    // one-time: ws[k][g*8+j] = w_hh[g*G + j0+j][k]
    for (int row = 0; row < 24; ++row) {
        const float* src = w_hh + ((size_t)(row >> 3) * G_ + j0 + (row & 7)) * G_;
        for (int k = tid; k < G_; k += 512) ws[k * 24 + row] = src[k];
    }
    __syncthreads();

    // mainloop coords: lane = (jl 0..7, bq 0..3); 4 local b per lane
    const int jl = lane >> 2;
    const int bq = lane & 3;
    const int b0 = bq * 4;

    // epilogue coords (threads 0..127): j = tid>>4, local b = tid&15
    const int jrow = tid >> 4;
    const int bl   = tid & 15;
    const int je   = j0 + jrow;
    float bhr = 0.f, bhz = 0.f, bhn = 0.f;
    if (tid < 128) {
        bhr = b_hh[je];
        bhz = b_hh[G_  + je];
        bhn = b_hh[2*G_ + je];
    }

    for (int t = 0; t < T_; ++t) {
        const int cur = t & 1, nxt = cur ^ 1;
        const float* hg = g_h + cur * (G_ * B_);
        float* hn = g_h + nxt * (G_ * B_);
        float* ho = g_hs2 + (size_t)(t >> 1) * G_ * 64;
        const unsigned gen_next = (t == T_ - 1) ? 0u : (unsigned)(t + 1);

        // gx prefetch for BOTH halves (independent of barriers)
        float pgrA=0.f, pgzA=0.f, pgnA=0.f, pgrB=0.f, pgzB=0.f, pgnB=0.f;
        if (tid < 128) {
            const float* gxp = g_gx + (size_t)t * G3_ * B_;
            pgrA = __ldcs(gxp + (size_t)je * B_            + bl);
            pgzA = __ldcs(gxp + (size_t)(G_   + je) * B_   + bl);
            pgnA = __ldcs(gxp + (size_t)(2*G_ + je) * B_   + bl);
            pgrB = __ldcs(gxp + (size_t)je * B_            + 16 + bl);
            pgzB = __ldcs(gxp + (size_t)(G_   + je) * B_   + 16 + bl);
            pgnB = __ldcs(gxp + (size_t)(2*G_ + je) * B_   + 16 + bl);
        }

        // ================= half A (b 0..15) =================
        if (tid == 0) { while (ld_acquire(&g_genA.v) < (unsigned)t) __nanosleep(32); }
        __syncthreads();

        {   // cp.async hsA <- g_h[cur][k0..k0+55][0..16)
            const float* src = hg + k0 * 32;
            float* dst = hsA + k0 * 16;
#pragma unroll
            for (int i = 0; i < 3; ++i) {
                int c = i * 32 + lane;
                cp_async16(dst + (c >> 2) * 16 + (c & 3) * 4,
                           src + (c >> 2) * 32 + (c & 3) * 4);
            }
            CP_COMMIT();
#pragma unroll
            for (int i = 3; i < 7; ++i) {
                int c = i * 32 + lane;
                cp_async16(dst + (c >> 2) * 16 + (c & 3) * 4,
                           src + (c >> 2) * 32 + (c & 3) * 4);
            }
            CP_COMMIT();
        }
        float pholdA = 0.f;
        if (tid < 128) pholdA = __ldcg(hg + je * 32 + bl);

        u64 ar0=0, ar1=0, az0=0, az1=0, an0=0, an1=0;
        CP_WAIT(1);
        __syncwarp();
        {
            const float* wp = ws + (size_t)k0 * 24 + jl;
            const u64*   hp = (const u64*)(hsA + (size_t)k0 * 16 + b0);
#pragma unroll 4
            for (int k = 0; k < 24; ++k) {
                float wr = wp[0], wz = wp[8], wn = wp[16];
                u64 h0 = hp[0], h1 = hp[1];
                u64 wrd = pack2(wr, wr), wzd = pack2(wz, wz), wnd = pack2(wn, wn);
                fma2(ar0, wrd, h0); fma2(ar1, wrd, h1);
                fma2(az0, wzd, h0); fma2(az1, wzd, h1);
                fma2(an0, wnd, h0); fma2(an1, wnd, h1);
                wp += 24; hp += 8;
            }
        }
        CP_WAIT(0);
        __syncwarp();
        {
            const float* wp = ws + (size_t)(k0 + 24) * 24 + jl;
            const u64*   hp = (const u64*)(hsA + (size_t)(k0 + 24) * 16 + b0);
#pragma unroll 4
            for (int k = 0; k < 32; ++k) {
                float wr = wp[0], wz = wp[8], wn = wp[16];
                u64 h0 = hp[0], h1 = hp[1];
                u64 wrd = pack2(wr, wr), wzd = pack2(wz, wz), wnd = pack2(wn, wn);
                fma2(ar0, wrd, h0); fma2(ar1, wrd, h1);
                fma2(az0, wzd, h0); fma2(az1, wzd, h1);
                fma2(an0, wnd, h0); fma2(an1, wnd, h1);
                wp += 24; hp += 8;
            }
        }
        __syncthreads();   // hsA dead; redA may overwrite
        {
            u64* rp = redA + ((size_t)(warp * 3 * 8) + jl) * 17 + bq * 2;
            rp[0] = ar0;            rp[1] = ar1;
            rp[8*17] = az0;         rp[8*17 + 1] = az1;
            rp[16*17] = an0;        rp[16*17 + 1] = an1;
        }
        __syncthreads();
        if (tid < 128) {
            float sr = 0.f, sz = 0.f, sn = 0.f;
#pragma unroll
            for (int w = 0; w < 16; ++w) {
                const float* rf = redAf + ((size_t)(w * 3 * 8) + jrow) * 34 + bl;
                sr += rf[0];
                sz += rf[8 * 34];
                sn += rf[16 * 34];
            }
            float r = sigm(pgrA + sr + bhr);
            float z = sigm(pgzA + sz + bhz);
            float n = tanh_fast(pgnA + r * (sn + bhn));
            float h = (1.0f - z) * n + z * pholdA;
            hn[je * 32 + bl] = h;
            ho[(size_t)je * 64 + bl * 2 + (t & 1)] = h;
        }
        __syncthreads();
        if (tid == 0) {
            unsigned old = atom_add_acqrel(&g_cntA.v);
            if (old == NB - 1) { st_relaxed(&g_cntA.v, 0); st_release(&g_genA.v, gen_next); }
        }

        // ================= half B (b 16..31) =================
        if (tid == 0) { while (ld_acquire(&g_genB.v) < (unsigned)t) __nanosleep(32); }
        __syncthreads();

        {   // cp.async hsB <- g_h[cur][k0..k0+55][16..32)
            const float* src = hg + k0 * 32 + 16;
            float* dst = hsB + k0 * 16;
#pragma unroll
            for (int i = 0; i < 3; ++i) {
                int c = i * 32 + lane;
                cp_async16(dst + (c >> 2) * 16 + (c & 3) * 4,
                           src + (c >> 2) * 32 + (c & 3) * 4);
            }
            CP_COMMIT();
#pragma unroll
            for (int i = 3; i < 7; ++i) {
                int c = i * 32 + lane;
                cp_async16(dst + (c >> 2) * 16 + (c & 3) * 4,
                           src + (c >> 2) * 32 + (c & 3) * 4);
            }
            CP_COMMIT();
        }
        float pholdB = 0.f;
        if (tid < 128) pholdB = __ldcg(hg + je * 32 + 16 + bl);

        ar0=0; ar1=0; az0=0; az1=0; an0=0; an1=0;
        CP_WAIT(1);
        __syncwarp();
        {
            const float* wp = ws + (size_t)k0 * 24 + jl;
            const u64*   hp = (const u64*)(hsB + (size_t)k0 * 16 + b0);
#pragma unroll 4
            for (int k = 0; k < 24; ++k) {
                float wr = wp[0], wz = wp[8], wn = wp[16];
                u64 h0 = hp[0], h1 = hp[1];
                u64 wrd = pack2(wr, wr), wzd = pack2(wz, wz), wnd = pack2(wn, wn);
                fma2(ar0, wrd, h0); fma2(ar1, wrd, h1);
                fma2(az0, wzd, h0); fma2(az1, wzd, h1);
                fma2(an0, wnd, h0); fma2(an1, wnd, h1);
                wp += 24; hp += 8;
            }
        }
        CP_WAIT(0);
        __syncwarp();
        {
            const float* wp = ws + (size_t)(k0 + 24) * 24 + jl;
            const u64*   hp = (const u64*)(hsB + (size_t)(k0 + 24) * 16 + b0);
#pragma unroll 4
            for (int k = 0; k < 32; ++k) {
                float wr = wp[0], wz = wp[8], wn = wp[16];
                u64 h0 = hp[0], h1 = hp[1];
                u64 wrd = pack2(wr, wr), wzd = pack2(wz, wz), wnd = pack2(wn, wn);
                fma2(ar0, wrd, h0); fma2(ar1, wrd, h1);
                fma2(az0, wzd, h0); fma2(az1, wzd, h1);
                fma2(an0, wnd, h0); fma2(an1, wnd, h1);
                wp += 24; hp += 8;
            }
        }
        __syncthreads();   // hsB dead; redB may overwrite
        {
            u64* rp = redB + ((size_t)(warp * 3 * 8) + jl) * 17 + bq * 2;
            rp[0] = ar0;            rp[1] = ar1;
            rp[8*17] = az0;         rp[8*17 + 1] = az1;
            rp[16*17] = an0;        rp[16*17 + 1] = an1;
        }
        __syncthreads();
        if (tid < 128) {
            float sr = 0.f, sz = 0.f, sn = 0.f;
#pragma unroll
            for (int w = 0; w < 16; ++w) {
                const float* rf = redBf + ((size_t)(w * 3 * 8) + jrow) * 34 + bl;
                sr += rf[0];
                sz += rf[8 * 34];
                sn += rf[16 * 34];
            }
            float r = sigm(pgrB + sr + bhr);
            float z = sigm(pgzB + sz + bhz);
            float n = tanh_fast(pgnB + r * (sn + bhn));
            float h = (1.0f - z) * n + z * pholdB;
            hn[je * 32 + 16 + bl] = h;
            ho[(size_t)je * 64 + (16 + bl) * 2 + (t & 1)] = h;
        }
        __syncthreads();
        if (tid == 0) {
            unsigned old = atom_add_acqrel(&g_cntB.v);
            if (old == NB - 1) { st_relaxed(&g_cntB.v, 0); st_release(&g_genB.v, gen_next); }
        }
    }
}

// ============================================================================
// out[b][t][h] = relu(sum_g hs[t][g][b] * w_post[h][g] + b_post[h])
// t-pairs in f32x2 lanes. grid (14 h-tiles, 512 t-pairs), 128 threads.
// ============================================================================
__global__ __launch_bounds__(128) void k_post(const float* __restrict__ w_post,
                                              const float* __restrict__ b_post,
                                              float* __restrict__ out) {
    __shared__ float wt [64 * 64];   // [k][h]
    __shared__ float ht2[64 * 64];   // [k][b*2]
    const int tid = threadIdx.x;
    const int hb  = blockIdx.x * 64;
    const int tp  = blockIdx.y;
    const int ht  = tid >> 3;
    const int bt  = tid & 7;
    const int hh  = ht * 4;
    const int b0  = bt * 4;

    u64 acc[4][4];
#pragma unroll
    for (int i = 0; i < 4; ++i)
#pragma unroll
        for (int j = 0; j < 4; ++j) acc[i][j] = 0ull;

    for (int ch = 0; ch < 14; ++ch) {
        const int g0 = ch * 64;
        for (int i = tid; i < 64 * 16; i += 128) {
            int r = i >> 4, cq = (i & 15) * 4;
            float4 v = *(const float4*)(w_post + (size_t)(hb + r) * G_ + g0 + cq);
            wt[(cq+0)*64 + r] = v.x; wt[(cq+1)*64 + r] = v.y;
            wt[(cq+2)*64 + r] = v.z; wt[(cq+3)*64 + r] = v.w;
        }
        const float* src = g_hs2 + ((size_t)tp * G_ + g0) * 64;
        for (int i = tid * 4; i < 4096; i += 512)
            *(float4*)(ht2 + i) = *(const float4*)(src + i);
        __syncthreads();

#pragma unroll 4
        for (int k = 0; k < 64; ++k) {
            float4 w4 = *(const float4*)(wt + k * 64 + hh);
            u64 wd0 = pack2(w4.x, w4.x), wd1 = pack2(w4.y, w4.y);
            u64 wd2 = pack2(w4.z, w4.z), wd3 = pack2(w4.w, w4.w);
            const u64* hp = (const u64*)(ht2 + k * 64 + b0 * 2);
            u64 h0 = hp[0], h1 = hp[1], h2 = hp[2], h3 = hp[3];
            fma2(acc[0][0], wd0, h0); fma2(acc[0][1], wd0, h1);
            fma2(acc[0][2], wd0, h2); fma2(acc[0][3], wd0, h3);
            fma2(acc[1][0], wd1, h0); fma2(acc[1][1], wd1, h1);
            fma2(acc[1][2], wd1, h2); fma2(acc[1][3], wd1, h3);
            fma2(acc[2][0], wd2, h0); fma2(acc[2][1], wd2, h1);
            fma2(acc[2][2], wd2, h2); fma2(acc[2][3], wd2, h3);
            fma2(acc[3][0], wd3, h0); fma2(acc[3][1], wd3, h1);
            fma2(acc[3][2], wd3, h2); fma2(acc[3][3], wd3, h3);
        }
        __syncthreads();
    }

    const int t0 = tp * 2, t1 = t0 + 1;
    float bi0 = b_post[hb + hh + 0], bi1 = b_post[hb + hh + 1];
    float bi2 = b_post[hb + hh + 2], bi3 = b_post[hb + hh + 3];
#pragma unroll
    for (int j = 0; j < 4; ++j) {
        int b = b0 + j;
        float2 a0 = unpack2(acc[0][j]), a1 = unpack2(acc[1][j]);
        float2 a2 = unpack2(acc[2][j]), a3 = unpack2(acc[3][j]);
        float4 o0 = make_float4(fmaxf(a0.x + bi0, 0.f), fmaxf(a1.x + bi1, 0.f),
                                fmaxf(a2.x + bi2, 0.f), fmaxf(a3.x + bi3, 0.f));
        float4 o1 = make_float4(fmaxf(a0.y + bi0, 0.f), fmaxf(a1.y + bi1, 0.f),
                                fmaxf(a2.y + bi2, 0.f), fmaxf(a3.y + bi3, 0.f));
        *(float4*)(out + ((size_t)b * T_ + t0) * H_ + hb + hh) = o0;
        *(float4*)(out + ((size_t)b * T_ + t1) * H_ + hb + hh) = o1;
    }
}

// ============================================================================
__global__ void k_last(float* __restrict__ out) {
    int i = blockIdx.x * blockDim.x + threadIdx.x;
    if (i < G_ * B_) {
        int b = i / G_, g = i % G_;
        out[(size_t)B_ * T_ * H_ + i] = g_h[g * 32 + b];
    }
}

// ============================================================================
extern "C" void kernel_launch(void* const* d_in, const int* in_sizes, int n_in,
                              void* d_out, int out_size) {
    const float* x      = (const float*)d_in[0];
    const float* state  = (const float*)d_in[1];
    const float* w_ih   = (const float*)d_in[2];
    const float* w_hh   = (const float*)d_in[3];
    const float* b_ih   = (const float*)d_in[4];
    const float* b_hh   = (const float*)d_in[5];
    const float* w_post = (const float*)d_in[6];
    const float* b_post = (const float*)d_in[7];
    float* out = (float*)d_out;

    static int smem_set = 0;
    if (!smem_set) {
        cudaFuncSetAttribute(k_rnn, cudaFuncAttributeMaxDynamicSharedMemorySize, RNN_SMEM);
        smem_set = 1;
    }

    // k_rnn is the 4th launch: ncu captures launch #4.
    k_gx  <<<dim3(42, 1024), 128>>>(x, state, w_ih, b_ih);
    k_nop <<<1, 32>>>();
    k_nop <<<1, 32>>>();
    k_rnn <<<NB, 512, RNN_SMEM>>>(w_hh, b_hh);
    k_post<<<dim3(14, 512), 128>>>(w_post, b_post, out);
    k_last<<<112, 256>>>(out);
}

// round 13
// speedup vs baseline: 1.2276x; 1.2276x over previous
#include <cuda_runtime.h>
#include <math.h>

#define B_  32
#define T_  1024
#define C_  128
#define G_  896
#define G3_ 2688
#define H_  896
#define NB  112      // persistent CTAs for the scan (1/SM guaranteed by smem)
#define TPC 4        // timesteps per k_gx CTA

typedef unsigned long long u64;

// ---------------- device scratch (allocation-free: __device__ globals) -------
__device__ __align__(256) float g_gx [(size_t)T_ * G3_ * B_];  // [T][3G][B]
__device__ __align__(256) float g_hs2[(size_t)T_ * G_  * B_];  // [t/2][G][B][2]
__device__ __align__(256) float g_h  [2 * G_ * B_];            // double-buffered h, [G][B]
__device__ unsigned g_bar_count = 0;
__device__ volatile unsigned g_bar_gen = 0;

// ---------------- helpers ----------------------------------------------------
__device__ __forceinline__ void fma2(u64 &acc, u64 a, u64 b) {
    asm("fma.rn.f32x2 %0, %1, %2, %0;" : "+l"(acc) : "l"(a), "l"(b));
}
__device__ __forceinline__ u64 pack2(float x, float y) {
    u64 r; asm("mov.b64 %0, {%1,%2};" : "=l"(r) : "f"(x), "f"(y)); return r;
}
__device__ __forceinline__ float2 unpack2(u64 v) {
    float2 r; asm("mov.b64 {%0,%1}, %2;" : "=f"(r.x), "=f"(r.y) : "l"(v)); return r;
}
__device__ __forceinline__ float sigm(float x) {
    return __fdividef(1.0f, 1.0f + __expf(-x));
}
__device__ __forceinline__ float tanh_fast(float x) {
    float e = __expf(2.0f * x);
    return 1.0f - __fdividef(2.0f, e + 1.0f);
}
__device__ __forceinline__ void cp_async16(float* smem_dst, const float* gsrc) {
    unsigned s = (unsigned)__cvta_generic_to_shared(smem_dst);
    asm volatile("cp.async.cg.shared.global [%0], [%1], 16;" :: "r"(s), "l"(gsrc));
}
#define CP_COMMIT() asm volatile("cp.async.commit_group;")
#define CP_WAIT(n)  asm volatile("cp.async.wait_group %0;" :: "n"(n))

// ============================================================================
__global__ void k_nop() {}

// ============================================================================
// gx[t][row][b] = b_ih[row] + sum_c x[b][t][c] * w_ih[row][c]
// grid (42 row-tiles of 64, 256 t-groups of TPC=4), 128 threads, 64KB dyn smem.
// Row-PAIRS live in the f32x2 lanes (w loads are direct LDS.64); x is stored
// pre-duplicated ({v,v} u64) so the mainloop has ZERO pack MOVs:
// per k = 6 LDS.64 + 8 FFMA2 -> fma-bound. w-tile fill amortized over 4 t.
// ============================================================================
#define GX_SMEM (65536)

__global__ __launch_bounds__(128) void k_gx(const float* __restrict__ x,
                                            const float* __restrict__ state,
                                            const float* __restrict__ w_ih,
                                            const float* __restrict__ b_ih) {
    extern __shared__ float gxsm[];
    float* ws  = gxsm;                 // [k][64 r] float (row-pairs adjacent)
    u64*   xsu = (u64*)(gxsm + 128 * 64);  // [k][32 b] dup-pairs {v,v}

    const int tid = threadIdx.x;
    const int r0  = blockIdx.x * 64;
    const int tb  = blockIdx.y * TPC;

    if (blockIdx.x == 0 && blockIdx.y == 0) {
        for (int i = tid; i < G_ * B_; i += 128) {
            int g = i >> 5, b = i & 31;
            g_h[g * 32 + b] = state[b * G_ + g];
        }
    }

    // one-time w fill: ws[k][r] = w_ih[r0+r][k]
    for (int i = tid; i < 64 * 32; i += 128) {
        int r = i >> 5, cq = (i & 31) * 4;
        float4 v = *(const float4*)(w_ih + (size_t)(r0 + r) * C_ + cq);
        ws[(cq+0)*64 + r] = v.x; ws[(cq+1)*64 + r] = v.y;
        ws[(cq+2)*64 + r] = v.z; ws[(cq+3)*64 + r] = v.w;
    }

    const int rt = tid >> 3;        // 0..15 -> rows rr..rr+3 (2 row-pairs)
    const int bt = tid & 7;         // 0..7  -> b bb..bb+3
    const int rr = rt * 4;
    const int bb = bt * 4;

    float bias[4];
#pragma unroll
    for (int i = 0; i < 4; ++i) bias[i] = b_ih[r0 + rr + i];

    for (int tt = 0; tt < TPC; ++tt) {
        const int t = tb + tt;
        __syncthreads();   // ws ready (tt=0) / previous mainloop done reading xsu

        // x fill, duplicated: xsu[c][b] = {x, x}. lane b varies -> conflict-free
        for (int i = tid; i < 32 * 32; i += 128) {
            int b = i & 31, cq = (i >> 5) * 4;
            float4 v = *(const float4*)(x + ((size_t)b * T_ + t) * C_ + cq);
            xsu[(cq+0) * 32 + b] = pack2(v.x, v.x);
            xsu[(cq+1) * 32 + b] = pack2(v.y, v.y);
            xsu[(cq+2) * 32 + b] = pack2(v.z, v.z);
            xsu[(cq+3) * 32 + b] = pack2(v.w, v.w);
        }
        __syncthreads();

        u64 acc[2][4];
#pragma unroll
        for (int p = 0; p < 2; ++p)
#pragma unroll
            for (int j = 0; j < 4; ++j) acc[p][j] = 0ull;

        const float* wp = ws + rr;
        const u64*   xp = xsu + bb;
#pragma unroll 4
        for (int k = 0; k < 128; ++k) {
            u64 w01 = *(const u64*)(wp);        // rows rr, rr+1
            u64 w23 = *(const u64*)(wp + 2);    // rows rr+2, rr+3
            u64 x0 = xp[0], x1 = xp[1], x2 = xp[2], x3 = xp[3];
            fma2(acc[0][0], w01, x0); fma2(acc[0][1], w01, x1);
            fma2(acc[0][2], w01, x2); fma2(acc[0][3], w01, x3);
            fma2(acc[1][0], w23, x0); fma2(acc[1][1], w23, x1);
            fma2(acc[1][2], w23, x2); fma2(acc[1][3], w23, x3);
            wp += 64; xp += 32;
        }

        // acc[p][j]: (.x = row rr+2p, .y = row rr+2p+1) for b = bb+j
        float2 av[2][4];
#pragma unroll
        for (int p = 0; p < 2; ++p)
#pragma unroll
            for (int j = 0; j < 4; ++j) av[p][j] = unpack2(acc[p][j]);

#pragma unroll
        for (int i = 0; i < 4; ++i) {
            const int p = i >> 1;
            float4 o;
            if (i & 1) o = make_float4(av[p][0].y, av[p][1].y, av[p][2].y, av[p][3].y);
            else       o = make_float4(av[p][0].x, av[p][1].x, av[p][2].x, av[p][3].x);
            o.x += bias[i]; o.y += bias[i]; o.z += bias[i]; o.w += bias[i];
            *(float4*)(g_gx + ((size_t)t * G3_ + r0 + rr + i) * B_ + bb) = o;
        }
    }
}

// ============================================================================
// Persistent GRU scan — TRUE round-6 winner (13186 us run): 112 CTAs x 256
// threads (8 warps). Warp w owns k-slice [w*112, w*112+112): cp.asyncs its
// FULL slice (2 groups of 56 rows = 14+14 cp_async16 per lane — R10/R11
// mistakenly copied only half, reading stale smem). Lane = (jl, bq): 1 j x
// 8 b x 3 gates, b-pairs in f32x2 lanes. Partials in dedicated smem;
// epilogue on all 256 threads. + protective sync after the ws fill.
// SMEM: hs 114688 + ws 86016 + red 24576 = 225280 -> 1 CTA/SM.
// ============================================================================
#define RNN_SMEM ((G_*B_ + 896*24 + 8*3*8*16*2) * 4)   // 225280

__global__ __launch_bounds__(256) void k_rnn(const float* __restrict__ w_hh,
                                             const float* __restrict__ b_hh) {
    extern __shared__ float sm[];
    float* hs   = sm;                         // [896][32]
    float* ws   = sm + G_ * B_;               // [896][24]  ws[k][g*8+j]
    u64*   redp = (u64*)(ws + 896 * 24);      // [8 w][3 g][8 j][16 bp]
    float* redf = (float*)redp;

    const int tid  = threadIdx.x;
    const int warp = tid >> 5;
    const int lane = tid & 31;
    const int cta  = blockIdx.x;
    const int j0   = cta * 8;
    const int k0   = warp * 112;

    for (int row = 0; row < 24; ++row) {
        const float* src = w_hh + ((size_t)(row >> 3) * G_ + j0 + (row & 7)) * G_;
        for (int k = tid; k < G_; k += 256) ws[k * 24 + row] = src[k];
    }
    __syncthreads();   // ws fully written before any warp's first mainloop

    const int jl = lane >> 2;
    const int bq = lane & 3;
    const int b0 = bq * 8;

    const int je  = j0 + warp;
    const float bhr = b_hh[je];
    const float bhz = b_hh[G_  + je];
    const float bhn = b_hh[2*G_ + je];

    for (int t = 0; t < T_; ++t) {
        const int cur = t & 1, nxt = cur ^ 1;
        const float* hg = g_h + cur * (G_ * B_);

        const float* gxp = g_gx + (size_t)t * G3_ * B_ + lane;
        float pgr   = __ldcs(gxp + (size_t)je * B_);
        float pgz   = __ldcs(gxp + (size_t)(G_ + je) * B_);
        float pgn   = __ldcs(gxp + (size_t)(2 * G_ + je) * B_);
        float phold = __ldcg(hg + je * 32 + lane);

        // warp-private h slice: 112 rows via cp.async.cg, 2 groups of 56 rows
        {
            const float* src = hg + k0 * 32;
            float* dst = hs + k0 * 32;
#pragma unroll
            for (int i = 0; i < 14; ++i)
                cp_async16(dst + (i * 32 + lane) * 4, src + (i * 32 + lane) * 4);
            CP_COMMIT();
#pragma unroll
            for (int i = 14; i < 28; ++i)
                cp_async16(dst + (i * 32 + lane) * 4, src + (i * 32 + lane) * 4);
            CP_COMMIT();
        }

        u64 ar[4] = {}, az[4] = {}, an[4] = {};

        CP_WAIT(1);          // group A (rows k0..k0+55) ready
        __syncwarp();
        {
            const float* wp = ws + (size_t)k0 * 24 + jl;
            const u64*   hp = (const u64*)(hs + (size_t)k0 * 32 + b0);
#pragma unroll 4
            for (int k = 0; k < 56; ++k) {
                float wr = wp[0], wz = wp[8], wn = wp[16];
                u64 h0 = hp[0], h1 = hp[1], h2 = hp[2], h3 = hp[3];
                u64 wrd = pack2(wr, wr), wzd = pack2(wz, wz), wnd = pack2(wn, wn);
                fma2(ar[0], wrd, h0); fma2(ar[1], wrd, h1);
                fma2(ar[2], wrd, h2); fma2(ar[3], wrd, h3);
                fma2(az[0], wzd, h0); fma2(az[1], wzd, h1);
                fma2(az[2], wzd, h2); fma2(az[3], wzd, h3);
                fma2(an[0], wnd, h0); fma2(an[1], wnd, h1);
                fma2(an[2], wnd, h2); fma2(an[3], wnd, h3);
                wp += 24; hp += 16;
            }
        }
        CP_WAIT(0);          // group B (rows k0+56..k0+111) ready
        __syncwarp();
        {
            const float* wp = ws + (size_t)(k0 + 56) * 24 + jl;
            const u64*   hp = (const u64*)(hs + (size_t)(k0 + 56) * 32 + b0);
#pragma unroll 4
            for (int k = 0; k < 56; ++k) {
                float wr = wp[0], wz = wp[8], wn = wp[16];
                u64 h0 = hp[0], h1 = hp[1], h2 = hp[2], h3 = hp[3];
                u64 wrd = pack2(wr, wr), wzd = pack2(wz, wz), wnd = pack2(wn, wn);
                fma2(ar[0], wrd, h0); fma2(ar[1], wrd, h1);
                fma2(ar[2], wrd, h2); fma2(ar[3], wrd, h3);
                fma2(az[0], wzd, h0); fma2(az[1], wzd, h1);
                fma2(az[2], wzd, h2); fma2(az[3], wzd, h3);
                fma2(an[0], wnd, h0); fma2(an[1], wnd, h1);
                fma2(an[2], wnd, h2); fma2(an[3], wnd, h3);
                wp += 24; hp += 16;
            }
        }

        // per-warp partials -> smem: red[w][g][jl][bp]
        {
            u64* rp = redp + (((size_t)warp * 3 * 8 + jl) * 16) + bq * 4;
#pragma unroll
            for (int i = 0; i < 4; ++i) rp[i]           = ar[i];
#pragma unroll
            for (int i = 0; i < 4; ++i) rp[8 * 16 + i]  = az[i];
#pragma unroll
            for (int i = 0; i < 4; ++i) rp[16 * 16 + i] = an[i];
        }
        __syncthreads();

        // epilogue: thread (j = warp, b = lane); partial reads are stride-1
        {
            float sr = 0.f, sz = 0.f, sn = 0.f;
#pragma unroll
            for (int w = 0; w < 8; ++w) {
                const float* rf = redf + (((size_t)w * 3 * 8) + warp) * 32 + lane;
                sr += rf[0];
                sz += rf[8 * 32];
                sn += rf[16 * 32];
            }
            float r = sigm(pgr + sr + bhr);
            float z = sigm(pgz + sz + bhz);
            float n = tanh_fast(pgn + r * (sn + bhn));
            float h = (1.0f - z) * n + z * phold;

            g_h[nxt * (G_ * B_) + je * 32 + lane] = h;
            g_hs2[(size_t)(t >> 1) * G_ * 64 + (size_t)je * 64 + lane * 2 + (t & 1)] = h;
            __threadfence();
        }

        // sense-reversing grid barrier (self-restoring -> replay-safe)
        __syncthreads();
        if (tid == 0) {
            unsigned old = g_bar_gen;
            if (atomicAdd(&g_bar_count, 1u) == NB - 1) {
                g_bar_count = 0;
                __threadfence();
                g_bar_gen = old + 1;
            } else {
                while (g_bar_gen == old) { __nanosleep(32); }
            }
            __threadfence();
        }
        __syncthreads();
    }
}

// ============================================================================
// out[b][t][h] = relu(sum_g hs[t][g][b] * w_post[h][g] + b_post[h])
// t-pairs in f32x2 lanes. grid (14 h-tiles, 512 t-pairs), 128 threads.
// ============================================================================
__global__ __launch_bounds__(128) void k_post(const float* __restrict__ w_post,
                                              const float* __restrict__ b_post,
                                              float* __restrict__ out) {
    __shared__ float wt [64 * 64];   // [k][h]
    __shared__ float ht2[64 * 64];   // [k][b*2]
    const int tid = threadIdx.x;
    const int hb  = blockIdx.x * 64;
    const int tp  = blockIdx.y;
    const int ht  = tid >> 3;
    const int bt  = tid & 7;
    const int hh  = ht * 4;
    const int b0  = bt * 4;

    u64 acc[4][4];
#pragma unroll
    for (int i = 0; i < 4; ++i)
#pragma unroll
        for (int j = 0; j < 4; ++j) acc[i][j] = 0ull;

    for (int ch = 0; ch < 14; ++ch) {
        const int g0 = ch * 64;
        for (int i = tid; i < 64 * 16; i += 128) {
            int r = i >> 4, cq = (i & 15) * 4;
            float4 v = *(const float4*)(w_post + (size_t)(hb + r) * G_ + g0 + cq);
            wt[(cq+0)*64 + r] = v.x; wt[(cq+1)*64 + r] = v.y;
            wt[(cq+2)*64 + r] = v.z; wt[(cq+3)*64 + r] = v.w;
        }
        const float* src = g_hs2 + ((size_t)tp * G_ + g0) * 64;
        for (int i = tid * 4; i < 4096; i += 512)
            *(float4*)(ht2 + i) = *(const float4*)(src + i);
        __syncthreads();

#pragma unroll 4
        for (int k = 0; k < 64; ++k) {
            float4 w4 = *(const float4*)(wt + k * 64 + hh);
            u64 wd0 = pack2(w4.x, w4.x), wd1 = pack2(w4.y, w4.y);
            u64 wd2 = pack2(w4.z, w4.z), wd3 = pack2(w4.w, w4.w);
            const u64* hp = (const u64*)(ht2 + k * 64 + b0 * 2);
            u64 h0 = hp[0], h1 = hp[1], h2 = hp[2], h3 = hp[3];
            fma2(acc[0][0], wd0, h0); fma2(acc[0][1], wd0, h1);
            fma2(acc[0][2], wd0, h2); fma2(acc[0][3], wd0, h3);
            fma2(acc[1][0], wd1, h0); fma2(acc[1][1], wd1, h1);
            fma2(acc[1][2], wd1, h2); fma2(acc[1][3], wd1, h3);
            fma2(acc[2][0], wd2, h0); fma2(acc[2][1], wd2, h1);
            fma2(acc[2][2], wd2, h2); fma2(acc[2][3], wd2, h3);
            fma2(acc[3][0], wd3, h0); fma2(acc[3][1], wd3, h1);
            fma2(acc[3][2], wd3, h2); fma2(acc[3][3], wd3, h3);
        }
        __syncthreads();
    }

    const int t0 = tp * 2, t1 = t0 + 1;
    float bi0 = b_post[hb + hh + 0], bi1 = b_post[hb + hh + 1];
    float bi2 = b_post[hb + hh + 2], bi3 = b_post[hb + hh + 3];
#pragma unroll
    for (int j = 0; j < 4; ++j) {
        int b = b0 + j;
        float2 a0 = unpack2(acc[0][j]), a1 = unpack2(acc[1][j]);
        float2 a2 = unpack2(acc[2][j]), a3 = unpack2(acc[3][j]);
        float4 o0 = make_float4(fmaxf(a0.x + bi0, 0.f), fmaxf(a1.x + bi1, 0.f),
                                fmaxf(a2.x + bi2, 0.f), fmaxf(a3.x + bi3, 0.f));
        float4 o1 = make_float4(fmaxf(a0.y + bi0, 0.f), fmaxf(a1.y + bi1, 0.f),
                                fmaxf(a2.y + bi2, 0.f), fmaxf(a3.y + bi3, 0.f));
        *(float4*)(out + ((size_t)b * T_ + t0) * H_ + hb + hh) = o0;
        *(float4*)(out + ((size_t)b * T_ + t1) * H_ + hb + hh) = o1;
    }
}

// ============================================================================
__global__ void k_last(float* __restrict__ out) {
    int i = blockIdx.x * blockDim.x + threadIdx.x;
    if (i < G_ * B_) {
        int b = i / G_, g = i % G_;
        out[(size_t)B_ * T_ * H_ + i] = g_h[g * 32 + b];
    }
}

// ============================================================================
extern "C" void kernel_launch(void* const* d_in, const int* in_sizes, int n_in,
                              void* d_out, int out_size) {
    const float* x      = (const float*)d_in[0];
    const float* state  = (const float*)d_in[1];
    const float* w_ih   = (const float*)d_in[2];
    const float* w_hh   = (const float*)d_in[3];
    const float* b_ih   = (const float*)d_in[4];
    const float* b_hh   = (const float*)d_in[5];
    const float* w_post = (const float*)d_in[6];
    const float* b_post = (const float*)d_in[7];
    float* out = (float*)d_out;

    static int smem_set = 0;
    if (!smem_set) {
        cudaFuncSetAttribute(k_rnn, cudaFuncAttributeMaxDynamicSharedMemorySize, RNN_SMEM);
        cudaFuncSetAttribute(k_gx,  cudaFuncAttributeMaxDynamicSharedMemorySize, GX_SMEM);
        smem_set = 1;
    }

    // k_rnn is the 4th launch: ncu captures launch #4.
    k_gx  <<<dim3(42, T_ / TPC), 128, GX_SMEM>>>(x, state, w_ih, b_ih);
    k_nop <<<1, 32>>>();
    k_nop <<<1, 32>>>();
    k_rnn <<<NB, 256, RNN_SMEM>>>(w_hh, b_hh);
    k_post<<<dim3(14, 512), 128>>>(w_post, b_post, out);
    k_last<<<112, 256>>>(out);
}

// round 15
// speedup vs baseline: 1.2980x; 1.0574x over previous
#include <cuda_runtime.h>
#include <math.h>

#define B_  32
#define T_  1024
#define C_  128
#define G_  896
#define G3_ 2688
#define H_  896
#define NB  112      // persistent CTAs for the scan (1/SM guaranteed by smem)
#define TPC 4        // timesteps per k_gx CTA

typedef unsigned long long u64;

// ---------------- device scratch (allocation-free: __device__ globals) -------
__device__ __align__(256) float g_gx [(size_t)T_ * G3_ * B_];  // [T][3G][B]
__device__ __align__(256) float g_hs2[(size_t)T_ * G_  * B_];  // [t/2][G][B][2]
__device__ __align__(256) float g_h  [2 * G_ * B_];            // double-buffered h, [G][B]
__device__ unsigned g_bar_count = 0;
__device__ volatile unsigned g_bar_gen = 0;

// ---------------- helpers ----------------------------------------------------
__device__ __forceinline__ void fma2(u64 &acc, u64 a, u64 b) {
    asm("fma.rn.f32x2 %0, %1, %2, %0;" : "+l"(acc) : "l"(a), "l"(b));
}
__device__ __forceinline__ u64 pack2(float x, float y) {
    u64 r; asm("mov.b64 %0, {%1,%2};" : "=l"(r) : "f"(x), "f"(y)); return r;
}
__device__ __forceinline__ float2 unpack2(u64 v) {
    float2 r; asm("mov.b64 {%0,%1}, %2;" : "=f"(r.x), "=f"(r.y) : "l"(v)); return r;
}
__device__ __forceinline__ float sigm(float x) {
    return __fdividef(1.0f, 1.0f + __expf(-x));
}
__device__ __forceinline__ float tanh_fast(float x) {
    float e = __expf(2.0f * x);
    return 1.0f - __fdividef(2.0f, e + 1.0f);
}
__device__ __forceinline__ void cp_async16(float* smem_dst, const float* gsrc) {
    unsigned s = (unsigned)__cvta_generic_to_shared(smem_dst);
    asm volatile("cp.async.cg.shared.global [%0], [%1], 16;" :: "r"(s), "l"(gsrc));
}
#define CP_COMMIT() asm volatile("cp.async.commit_group;")
#define CP_WAIT(n)  asm volatile("cp.async.wait_group %0;" :: "n"(n))

// ============================================================================
__global__ void k_nop() {}

// ============================================================================
// gx[t][row][b] = b_ih[row] + sum_c x[b][t][c] * w_ih[row][c]   (R12 verbatim)
// ============================================================================
#define GX_SMEM (65536)

__global__ __launch_bounds__(128) void k_gx(const float* __restrict__ x,
                                            const float* __restrict__ state,
                                            const float* __restrict__ w_ih,
                                            const float* __restrict__ b_ih) {
    extern __shared__ float gxsm[];
    float* ws  = gxsm;                 // [k][64 r] float (row-pairs adjacent)
    u64*   xsu = (u64*)(gxsm + 128 * 64);  // [k][32 b] dup-pairs {v,v}

    const int tid = threadIdx.x;
    const int r0  = blockIdx.x * 64;
    const int tb  = blockIdx.y * TPC;

    if (blockIdx.x == 0 && blockIdx.y == 0) {
        for (int i = tid; i < G_ * B_; i += 128) {
            int g = i >> 5, b = i & 31;
            g_h[g * 32 + b] = state[b * G_ + g];
        }
    }

    for (int i = tid; i < 64 * 32; i += 128) {
        int r = i >> 5, cq = (i & 31) * 4;
        float4 v = *(const float4*)(w_ih + (size_t)(r0 + r) * C_ + cq);
        ws[(cq+0)*64 + r] = v.x; ws[(cq+1)*64 + r] = v.y;
        ws[(cq+2)*64 + r] = v.z; ws[(cq+3)*64 + r] = v.w;
    }

    const int rt = tid >> 3;
    const int bt = tid & 7;
    const int rr = rt * 4;
    const int bb = bt * 4;

    float bias[4];
#pragma unroll
    for (int i = 0; i < 4; ++i) bias[i] = b_ih[r0 + rr + i];

    for (int tt = 0; tt < TPC; ++tt) {
        const int t = tb + tt;
        __syncthreads();

        for (int i = tid; i < 32 * 32; i += 128) {
            int b = i & 31, cq = (i >> 5) * 4;
            float4 v = *(const float4*)(x + ((size_t)b * T_ + t) * C_ + cq);
            xsu[(cq+0) * 32 + b] = pack2(v.x, v.x);
            xsu[(cq+1) * 32 + b] = pack2(v.y, v.y);
            xsu[(cq+2) * 32 + b] = pack2(v.z, v.z);
            xsu[(cq+3) * 32 + b] = pack2(v.w, v.w);
        }
        __syncthreads();

        u64 acc[2][4];
#pragma unroll
        for (int p = 0; p < 2; ++p)
#pragma unroll
            for (int j = 0; j < 4; ++j) acc[p][j] = 0ull;

        const float* wp = ws + rr;
        const u64*   xp = xsu + bb;
#pragma unroll 4
        for (int k = 0; k < 128; ++k) {
            u64 w01 = *(const u64*)(wp);
            u64 w23 = *(const u64*)(wp + 2);
            u64 x0 = xp[0], x1 = xp[1], x2 = xp[2], x3 = xp[3];
            fma2(acc[0][0], w01, x0); fma2(acc[0][1], w01, x1);
            fma2(acc[0][2], w01, x2); fma2(acc[0][3], w01, x3);
            fma2(acc[1][0], w23, x0); fma2(acc[1][1], w23, x1);
            fma2(acc[1][2], w23, x2); fma2(acc[1][3], w23, x3);
            wp += 64; xp += 32;
        }

        float2 av[2][4];
#pragma unroll
        for (int p = 0; p < 2; ++p)
#pragma unroll
            for (int j = 0; j < 4; ++j) av[p][j] = unpack2(acc[p][j]);

#pragma unroll
        for (int i = 0; i < 4; ++i) {
            const int p = i >> 1;
            float4 o;
            if (i & 1) o = make_float4(av[p][0].y, av[p][1].y, av[p][2].y, av[p][3].y);
            else       o = make_float4(av[p][0].x, av[p][1].x, av[p][2].x, av[p][3].x);
            o.x += bias[i]; o.y += bias[i]; o.z += bias[i]; o.w += bias[i];
            *(float4*)(g_gx + ((size_t)t * G3_ + r0 + rr + i) * B_ + bb) = o;
        }
    }
}

// ============================================================================
// Persistent GRU scan — R12 winner verbatim (measured 8.59 ms).
// ============================================================================
#define RNN_SMEM ((G_*B_ + 896*24 + 8*3*8*16*2) * 4)   // 225280

__global__ __launch_bounds__(256) void k_rnn(const float* __restrict__ w_hh,
                                             const float* __restrict__ b_hh) {
    extern __shared__ float sm[];
    float* hs   = sm;                         // [896][32]
    float* ws   = sm + G_ * B_;               // [896][24]  ws[k][g*8+j]
    u64*   redp = (u64*)(ws + 896 * 24);      // [8 w][3 g][8 j][16 bp]
    float* redf = (float*)redp;

    const int tid  = threadIdx.x;
    const int warp = tid >> 5;
    const int lane = tid & 31;
    const int cta  = blockIdx.x;
    const int j0   = cta * 8;
    const int k0   = warp * 112;

    for (int row = 0; row < 24; ++row) {
        const float* src = w_hh + ((size_t)(row >> 3) * G_ + j0 + (row & 7)) * G_;
        for (int k = tid; k < G_; k += 256) ws[k * 24 + row] = src[k];
    }
    __syncthreads();

    const int jl = lane >> 2;
    const int bq = lane & 3;
    const int b0 = bq * 8;

    const int je  = j0 + warp;
    const float bhr = b_hh[je];
    const float bhz = b_hh[G_  + je];
    const float bhn = b_hh[2*G_ + je];

    for (int t = 0; t < T_; ++t) {
        const int cur = t & 1, nxt = cur ^ 1;
        const float* hg = g_h + cur * (G_ * B_);

        const float* gxp = g_gx + (size_t)t * G3_ * B_ + lane;
        float pgr   = __ldcs(gxp + (size_t)je * B_);
        float pgz   = __ldcs(gxp + (size_t)(G_ + je) * B_);
        float pgn   = __ldcs(gxp + (size_t)(2 * G_ + je) * B_);
        float phold = __ldcg(hg + je * 32 + lane);

        {
            const float* src = hg + k0 * 32;
            float* dst = hs + k0 * 32;
#pragma unroll
            for (int i = 0; i < 14; ++i)
                cp_async16(dst + (i * 32 + lane) * 4, src + (i * 32 + lane) * 4);
            CP_COMMIT();
#pragma unroll
            for (int i = 14; i < 28; ++i)
                cp_async16(dst + (i * 32 + lane) * 4, src + (i * 32 + lane) * 4);
            CP_COMMIT();
        }

        u64 ar[4] = {}, az[4] = {}, an[4] = {};

        CP_WAIT(1);
        __syncwarp();
        {
            const float* wp = ws + (size_t)k0 * 24 + jl;
            const u64*   hp = (const u64*)(hs + (size_t)k0 * 32 + b0);
#pragma unroll 4
            for (int k = 0; k < 56; ++k) {
                float wr = wp[0], wz = wp[8], wn = wp[16];
                u64 h0 = hp[0], h1 = hp[1], h2 = hp[2], h3 = hp[3];
                u64 wrd = pack2(wr, wr), wzd = pack2(wz, wz), wnd = pack2(wn, wn);
                fma2(ar[0], wrd, h0); fma2(ar[1], wrd, h1);
                fma2(ar[2], wrd, h2); fma2(ar[3], wrd, h3);
                fma2(az[0], wzd, h0); fma2(az[1], wzd, h1);
                fma2(az[2], wzd, h2); fma2(az[3], wzd, h3);
                fma2(an[0], wnd, h0); fma2(an[1], wnd, h1);
                fma2(an[2], wnd, h2); fma2(an[3], wnd, h3);
                wp += 24; hp += 16;
            }
        }
        CP_WAIT(0);
        __syncwarp();
        {
            const float* wp = ws + (size_t)(k0 + 56) * 24 + jl;
            const u64*   hp = (const u64*)(hs + (size_t)(k0 + 56) * 32 + b0);
#pragma unroll 4
            for (int k = 0; k < 56; ++k) {
                float wr = wp[0], wz = wp[8], wn = wp[16];
                u64 h0 = hp[0], h1 = hp[1], h2 = hp[2], h3 = hp[3];
                u64 wrd = pack2(wr, wr), wzd = pack2(wz, wz), wnd = pack2(wn, wn);
                fma2(ar[0], wrd, h0); fma2(ar[1], wrd, h1);
                fma2(ar[2], wrd, h2); fma2(ar[3], wrd, h3);
                fma2(az[0], wzd, h0); fma2(az[1], wzd, h1);
                fma2(az[2], wzd, h2); fma2(az[3], wzd, h3);
                fma2(an[0], wnd, h0); fma2(an[1], wnd, h1);
                fma2(an[2], wnd, h2); fma2(an[3], wnd, h3);
                wp += 24; hp += 16;
            }
        }

        {
            u64* rp = redp + (((size_t)warp * 3 * 8 + jl) * 16) + bq * 4;
#pragma unroll
            for (int i = 0; i < 4; ++i) rp[i]           = ar[i];
#pragma unroll
            for (int i = 0; i < 4; ++i) rp[8 * 16 + i]  = az[i];
#pragma unroll
            for (int i = 0; i < 4; ++i) rp[16 * 16 + i] = an[i];
        }
        __syncthreads();

        {
            float sr = 0.f, sz = 0.f, sn = 0.f;
#pragma unroll
            for (int w = 0; w < 8; ++w) {
                const float* rf = redf + (((size_t)w * 3 * 8) + warp) * 32 + lane;
                sr += rf[0];
                sz += rf[8 * 32];
                sn += rf[16 * 32];
            }
            float r = sigm(pgr + sr + bhr);
            float z = sigm(pgz + sz + bhz);
            float n = tanh_fast(pgn + r * (sn + bhn));
            float h = (1.0f - z) * n + z * phold;

            g_h[nxt * (G_ * B_) + je * 32 + lane] = h;
            g_hs2[(size_t)(t >> 1) * G_ * 64 + (size_t)je * 64 + lane * 2 + (t & 1)] = h;
            __threadfence();
        }

        __syncthreads();
        if (tid == 0) {
            unsigned old = g_bar_gen;
            if (atomicAdd(&g_bar_count, 1u) == NB - 1) {
                g_bar_count = 0;
                __threadfence();
                g_bar_gen = old + 1;
            } else {
                while (g_bar_gen == old) { __nanosleep(32); }
            }
            __threadfence();
        }
        __syncthreads();
    }
}

// ============================================================================
// out[b][t][h] = relu(sum_g hs[t][g][b] * w_post[h][g] + b_post[h])
// t-pairs in f32x2 lanes; thread tile 8h x 4b x 2t. CTA h-tile 128.
// grid (7 h-tiles, 512 t-pairs), 128 threads. DYNAMIC smem 48KB (opt-in).
// ============================================================================
#define POST_SMEM ((64 * 128 + 64 * 64) * 4)   // 49152

__global__ __launch_bounds__(128) void k_post(const float* __restrict__ w_post,
                                              const float* __restrict__ b_post,
                                              float* __restrict__ out) {
    extern __shared__ float psm[];
    float* wt  = psm;            // [64 k][128 h]
    float* ht2 = psm + 64 * 128; // [64 k][64 b*2]
    const int tid = threadIdx.x;
    const int hb  = blockIdx.x * 128;
    const int tp  = blockIdx.y;
    const int ht  = tid >> 3;        // 0..15
    const int bt  = tid & 7;         // 0..7
    const int hh  = ht * 8;
    const int b0  = bt * 4;

    u64 acc[8][4];
#pragma unroll
    for (int i = 0; i < 8; ++i)
#pragma unroll
        for (int j = 0; j < 4; ++j) acc[i][j] = 0ull;

    for (int ch = 0; ch < 14; ++ch) {
        const int g0 = ch * 64;
        for (int i = tid; i < 64 * 32; i += 128) {
            int r = i >> 4, cq = (i & 15) * 4;
            float4 v = *(const float4*)(w_post + (size_t)(hb + r) * G_ + g0 + cq);
            wt[(cq+0)*128 + r] = v.x; wt[(cq+1)*128 + r] = v.y;
            wt[(cq+2)*128 + r] = v.z; wt[(cq+3)*128 + r] = v.w;
        }
        const float* src = g_hs2 + ((size_t)tp * G_ + g0) * 64;
        for (int i = tid * 4; i < 4096; i += 512)
            *(float4*)(ht2 + i) = *(const float4*)(src + i);
        __syncthreads();

#pragma unroll 2
        for (int k = 0; k < 64; ++k) {
            float4 wa = *(const float4*)(wt + k * 128 + hh);
            float4 wb = *(const float4*)(wt + k * 128 + hh + 4);
            u64 wd[8];
            wd[0] = pack2(wa.x, wa.x); wd[1] = pack2(wa.y, wa.y);
            wd[2] = pack2(wa.z, wa.z); wd[3] = pack2(wa.w, wa.w);
            wd[4] = pack2(wb.x, wb.x); wd[5] = pack2(wb.y, wb.y);
            wd[6] = pack2(wb.z, wb.z); wd[7] = pack2(wb.w, wb.w);
            const u64* hp = (const u64*)(ht2 + k * 64 + b0 * 2);
            u64 h0 = hp[0], h1 = hp[1], h2 = hp[2], h3 = hp[3];
#pragma unroll
            for (int i = 0; i < 8; ++i) {
                fma2(acc[i][0], wd[i], h0); fma2(acc[i][1], wd[i], h1);
                fma2(acc[i][2], wd[i], h2); fma2(acc[i][3], wd[i], h3);
            }
        }
        __syncthreads();
    }

    const int t0 = tp * 2, t1 = t0 + 1;
    float bi[8];
#pragma unroll
    for (int i = 0; i < 8; ++i) bi[i] = b_post[hb + hh + i];
#pragma unroll
    for (int j = 0; j < 4; ++j) {
        int b = b0 + j;
        float2 a[8];
#pragma unroll
        for (int i = 0; i < 8; ++i) a[i] = unpack2(acc[i][j]);
        float4 o0a = make_float4(fmaxf(a[0].x + bi[0], 0.f), fmaxf(a[1].x + bi[1], 0.f),
                                 fmaxf(a[2].x + bi[2], 0.f), fmaxf(a[3].x + bi[3], 0.f));
        float4 o0b = make_float4(fmaxf(a[4].x + bi[4], 0.f), fmaxf(a[5].x + bi[5], 0.f),
                                 fmaxf(a[6].x + bi[6], 0.f), fmaxf(a[7].x + bi[7], 0.f));
        float4 o1a = make_float4(fmaxf(a[0].y + bi[0], 0.f), fmaxf(a[1].y + bi[1], 0.f),
                                 fmaxf(a[2].y + bi[2], 0.f), fmaxf(a[3].y + bi[3], 0.f));
        float4 o1b = make_float4(fmaxf(a[4].y + bi[4], 0.f), fmaxf(a[5].y + bi[5], 0.f),
                                 fmaxf(a[6].y + bi[6], 0.f), fmaxf(a[7].y + bi[7], 0.f));
        float* p0 = out + ((size_t)b * T_ + t0) * H_ + hb + hh;
        float* p1 = out + ((size_t)b * T_ + t1) * H_ + hb + hh;
        *(float4*)(p0)     = o0a;
        *(float4*)(p0 + 4) = o0b;
        *(float4*)(p1)     = o1a;
        *(float4*)(p1 + 4) = o1b;
    }
}

// ============================================================================
__global__ void k_last(float* __restrict__ out) {
    int i = blockIdx.x * blockDim.x + threadIdx.x;
    if (i < G_ * B_) {
        int b = i / G_, g = i % G_;
        out[(size_t)B_ * T_ * H_ + i] = g_h[g * 32 + b];
    }
}

// ============================================================================
extern "C" void kernel_launch(void* const* d_in, const int* in_sizes, int n_in,
                              void* d_out, int out_size) {
    const float* x      = (const float*)d_in[0];
    const float* state  = (const float*)d_in[1];
    const float* w_ih   = (const float*)d_in[2];
    const float* w_hh   = (const float*)d_in[3];
    const float* b_ih   = (const float*)d_in[4];
    const float* b_hh   = (const float*)d_in[5];
    const float* w_post = (const float*)d_in[6];
    const float* b_post = (const float*)d_in[7];
    float* out = (float*)d_out;

    static int smem_set = 0;
    if (!smem_set) {
        cudaFuncSetAttribute(k_rnn,  cudaFuncAttributeMaxDynamicSharedMemorySize, RNN_SMEM);
        cudaFuncSetAttribute(k_gx,   cudaFuncAttributeMaxDynamicSharedMemorySize, GX_SMEM);
        cudaFuncSetAttribute(k_post, cudaFuncAttributeMaxDynamicSharedMemorySize, POST_SMEM);
        smem_set = 1;
    }

    // k_post is the 4th launch this round: ncu captures launch #4.
    k_gx  <<<dim3(42, T_ / TPC), 128, GX_SMEM>>>(x, state, w_ih, b_ih);
    k_nop <<<1, 32>>>();
    k_rnn <<<NB, 256, RNN_SMEM>>>(w_hh, b_hh);
    k_post<<<dim3(7, 512), 128, POST_SMEM>>>(w_post, b_post, out);
    k_last<<<112, 256>>>(out);
}